// round 4
// baseline (speedup 1.0000x reference)
#include <cuda_runtime.h>

#define RADIUS_F 5.0f
#define ECONV_F  14.399645f
#define HALF_ECONV (0.5f * 14.399645f)
#define MAX_ATOMS_COMB 262144
#define MOL_BITS 11
#define MOL_MASK 0x7FFu

// Packed per-atom record: charge (f32, low 11 mantissa bits rounded to nearest)
// with mol index in those low 11 bits. One 4B gather gives qi+mol.
__device__ unsigned g_comb4[MAX_ATOMS_COMB];

__global__ void prep_kernel(const float* __restrict__ charges,
                            const int*   __restrict__ mol_index,
                            int n_atoms, int pack,
                            float* __restrict__ out, int n_mol)
{
    int i = blockIdx.x * blockDim.x + threadIdx.x;
    if (pack && i < n_atoms) {
        unsigned b = __float_as_uint(charges[i]);
        b += 0x400u;           // round-to-nearest on stolen bits
        b &= ~MOL_MASK;
        g_comb4[i] = b | (unsigned)mol_index[i];
    }
    if (i < n_mol) out[i] = 0.0f;
}

__device__ __forceinline__ float pair_energy(
    float r, int fi, int si,
    const float* __restrict__ charges, int& mol)
{
    unsigned b = g_comb4[fi];
    mol = (int)(b & MOL_MASK);
    float qi  = __uint_as_float(b & ~MOL_MASK);
    float qj  = __ldg(charges + si);
    float scr = 0.5f * (1.0f + cospif(r * (1.0f / RADIUS_F)));
    return qi * qj * __fdividef(scr, r);
}

__device__ __forceinline__ void accum_smem(
    float r, int fi, int si,
    const float* __restrict__ charges, float* __restrict__ bins)
{
    if (r < RADIUS_F) {
        int mol;
        float e = pair_energy(r, fi, si, charges, mol);
        atomicAdd(bins + mol, e);                 // smem ATOMS path
    }
}

__device__ __forceinline__ void accum_gmem(
    float r, int fi, int si,
    const float* __restrict__ charges, float* __restrict__ out)
{
    if (r < RADIUS_F) {
        int mol;
        float e = pair_energy(r, fi, si, charges, mol);
        atomicAdd(out + mol, HALF_ECONV * e);     // L2 RED path (no return)
    }
}

__global__ void __launch_bounds__(1024, 2)
pair_kernel(const float* __restrict__ pair_dist,
            const int*   __restrict__ pair_first,
            const int*   __restrict__ pair_second,
            const float* __restrict__ charges,
            float* __restrict__ out,
            int n_pairs, int n_mol)
{
    extern __shared__ float bins[];
    for (int b = threadIdx.x; b < n_mol; b += blockDim.x) bins[b] = 0.0f;
    __syncthreads();

    const int gtid   = blockIdx.x * blockDim.x + threadIdx.x;
    const int stride = gridDim.x * blockDim.x;
    const int n4     = n_pairs >> 2;

    const float4* __restrict__ pd4 = (const float4*)pair_dist;
    const int4*   __restrict__ pf4 = (const int4*)pair_first;
    const int4*   __restrict__ ps4 = (const int4*)pair_second;

    int it = 0;
    for (int i = gtid; i < n4; i += stride, it++) {
        float4 d = pd4[i];
        int4   f = pf4[i];
        int4   s = ps4[i];
        if ((it & 3) == 0) {   // 1/4 of iterations -> L2 RED path
            accum_gmem(d.x, f.x, s.x, charges, out);
            accum_gmem(d.y, f.y, s.y, charges, out);
            accum_gmem(d.z, f.z, s.z, charges, out);
            accum_gmem(d.w, f.w, s.w, charges, out);
        } else {               // 3/4 -> smem ATOMS path
            accum_smem(d.x, f.x, s.x, charges, bins);
            accum_smem(d.y, f.y, s.y, charges, bins);
            accum_smem(d.z, f.z, s.z, charges, bins);
            accum_smem(d.w, f.w, s.w, charges, bins);
        }
    }
    // tail (n_pairs not divisible by 4)
    for (int t = (n4 << 2) + gtid; t < n_pairs; t += stride) {
        accum_smem(pair_dist[t], pair_first[t], pair_second[t],
                   charges, bins);
    }

    __syncthreads();
    for (int b = threadIdx.x; b < n_mol; b += blockDim.x) {
        float v = bins[b];
        if (v != 0.0f) atomicAdd(out + b, HALF_ECONV * v);
    }
}

// ---- fallback path (shapes outside the fast-path assumptions) ----
__global__ void pair_kernel_global(const float* __restrict__ pair_dist,
                                   const int*   __restrict__ pair_first,
                                   const int*   __restrict__ pair_second,
                                   const float* __restrict__ charges,
                                   const int*   __restrict__ mol_index,
                                   float* __restrict__ out, int n_pairs)
{
    const int gtid   = blockIdx.x * blockDim.x + threadIdx.x;
    const int stride = gridDim.x * blockDim.x;
    for (int i = gtid; i < n_pairs; i += stride) {
        float r = pair_dist[i];
        if (r < RADIUS_F) {
            int   fi  = pair_first[i];
            float qi  = __ldg(charges + fi);
            int   mol = __ldg(mol_index + fi);
            float qj  = __ldg(charges + pair_second[i]);
            float scr = 0.5f * (1.0f + cospif(r * (1.0f / RADIUS_F)));
            float e   = HALF_ECONV * qi * qj * __fdividef(scr, r);
            atomicAdd(out + mol, e);
        }
    }
}

extern "C" void kernel_launch(void* const* d_in, const int* in_sizes, int n_in,
                              void* d_out, int out_size)
{
    const float* charges     = (const float*)d_in[0];
    const float* pair_dist   = (const float*)d_in[1];
    const int*   pair_first  = (const int*)d_in[2];
    const int*   pair_second = (const int*)d_in[3];
    const int*   mol_index   = (const int*)d_in[4];

    int n_atoms = in_sizes[0];
    int n_pairs = in_sizes[1];
    int n_mol   = out_size;
    float* out  = (float*)d_out;

    bool fast = (n_atoms <= MAX_ATOMS_COMB) &&
                (n_mol <= (1 << MOL_BITS)) &&
                ((size_t)n_mol * sizeof(float) <= 48 * 1024);

    int prep_n = n_atoms > n_mol ? n_atoms : n_mol;
    prep_kernel<<<(prep_n + 255) / 256, 256>>>(charges, mol_index, n_atoms,
                                               fast ? 1 : 0, out, n_mol);

    if (fast) {
        size_t smem = (size_t)n_mol * sizeof(float);
        pair_kernel<<<296, 1024, smem>>>(pair_dist, pair_first, pair_second,
                                         charges, out, n_pairs, n_mol);
    } else {
        pair_kernel_global<<<296, 1024>>>(pair_dist, pair_first, pair_second,
                                          charges, mol_index, out, n_pairs);
    }
}

// round 5
// speedup vs baseline: 3.1374x; 3.1374x over previous
#include <cuda_runtime.h>
#include <cuda_fp16.h>

#define RADIUS_F 5.0f
#define HALF_ECONV (0.5f * 14.399645f)
#define MAX_ATOMS_COMB 262144
#define MOL_BITS 11
#define MOL_MASK 0x7FFu

// Packed per-atom record: charge (f32, low 11 mantissa bits rounded to nearest)
// with mol index in those low 11 bits. One 4B L2 gather gives qi+mol.
__device__ unsigned g_comb4[MAX_ATOMS_COMB];

__global__ void prep_kernel(const float* __restrict__ charges,
                            const int*   __restrict__ mol_index,
                            int n_atoms, int pack,
                            float* __restrict__ out, int n_mol)
{
    int i = blockIdx.x * blockDim.x + threadIdx.x;
    if (pack && i < n_atoms) {
        unsigned b = __float_as_uint(charges[i]);
        b += 0x400u;           // round-to-nearest on stolen bits
        b &= ~MOL_MASK;
        g_comb4[i] = b | (unsigned)mol_index[i];
    }
    if (i < n_mol) out[i] = 0.0f;
}

__device__ __forceinline__ void accum_pair(
    float r, int fi, int si,
    const __half* __restrict__ qtab,   // fp16 charges in shared memory
    float* __restrict__ bins)
{
    if (r < RADIUS_F) {
        unsigned b = g_comb4[fi];              // L2-resident 4B gather
        int   mol = (int)(b & MOL_MASK);
        float qi  = __uint_as_float(b & ~MOL_MASK);
        float qj  = __half2float(qtab[si]);    // LDS gather (no L2 traffic)
        float scr = 0.5f * (1.0f + cospif(r * (1.0f / RADIUS_F)));
        float e   = qi * qj * __fdividef(scr, r);
        atomicAdd(bins + mol, e);
    }
}

__global__ void __launch_bounds__(1024, 1)
pair_kernel(const float* __restrict__ pair_dist,
            const int*   __restrict__ pair_first,
            const int*   __restrict__ pair_second,
            const float* __restrict__ charges,
            float* __restrict__ out,
            int n_pairs, int n_mol, int n_atoms)
{
    extern __shared__ char smem_raw[];
    float*  bins = (float*)smem_raw;
    __half* qtab = (__half*)(smem_raw + (size_t)n_mol * sizeof(float));

    for (int b = threadIdx.x; b < n_mol; b += blockDim.x) bins[b] = 0.0f;
    // load full charge table into smem as fp16 (vectorized)
    {
        int n4a = n_atoms >> 2;
        const float4* c4 = (const float4*)charges;
        __half2* q2 = (__half2*)qtab;
        for (int i = threadIdx.x; i < n4a; i += blockDim.x) {
            float4 c = c4[i];
            q2[2 * i]     = __floats2half2_rn(c.x, c.y);
            q2[2 * i + 1] = __floats2half2_rn(c.z, c.w);
        }
        for (int i = (n4a << 2) + threadIdx.x; i < n_atoms; i += blockDim.x)
            qtab[i] = __float2half_rn(charges[i]);
    }
    __syncthreads();

    const int gtid   = blockIdx.x * blockDim.x + threadIdx.x;
    const int stride = gridDim.x * blockDim.x;
    const int n4     = n_pairs >> 2;

    const float4* __restrict__ pd4 = (const float4*)pair_dist;
    const int4*   __restrict__ pf4 = (const int4*)pair_first;
    const int4*   __restrict__ ps4 = (const int4*)pair_second;

    for (int i = gtid; i < n4; i += stride) {
        float4 d = pd4[i];
        int4   f = pf4[i];
        int4   s = ps4[i];
        accum_pair(d.x, f.x, s.x, qtab, bins);
        accum_pair(d.y, f.y, s.y, qtab, bins);
        accum_pair(d.z, f.z, s.z, qtab, bins);
        accum_pair(d.w, f.w, s.w, qtab, bins);
    }
    for (int t = (n4 << 2) + gtid; t < n_pairs; t += stride) {
        accum_pair(pair_dist[t], pair_first[t], pair_second[t], qtab, bins);
    }

    __syncthreads();
    for (int b = threadIdx.x; b < n_mol; b += blockDim.x) {
        float v = bins[b];
        if (v != 0.0f) atomicAdd(out + b, HALF_ECONV * v);
    }
}

// ---- fallback path (shapes outside the fast-path assumptions) ----
__global__ void pair_kernel_global(const float* __restrict__ pair_dist,
                                   const int*   __restrict__ pair_first,
                                   const int*   __restrict__ pair_second,
                                   const float* __restrict__ charges,
                                   const int*   __restrict__ mol_index,
                                   float* __restrict__ out, int n_pairs)
{
    const int gtid   = blockIdx.x * blockDim.x + threadIdx.x;
    const int stride = gridDim.x * blockDim.x;
    for (int i = gtid; i < n_pairs; i += stride) {
        float r = pair_dist[i];
        if (r < RADIUS_F) {
            int   fi  = pair_first[i];
            float qi  = __ldg(charges + fi);
            int   mol = __ldg(mol_index + fi);
            float qj  = __ldg(charges + pair_second[i]);
            float scr = 0.5f * (1.0f + cospif(r * (1.0f / RADIUS_F)));
            float e   = HALF_ECONV * qi * qj * __fdividef(scr, r);
            atomicAdd(out + mol, e);
        }
    }
}

extern "C" void kernel_launch(void* const* d_in, const int* in_sizes, int n_in,
                              void* d_out, int out_size)
{
    const float* charges     = (const float*)d_in[0];
    const float* pair_dist   = (const float*)d_in[1];
    const int*   pair_first  = (const int*)d_in[2];
    const int*   pair_second = (const int*)d_in[3];
    const int*   mol_index   = (const int*)d_in[4];

    int n_atoms = in_sizes[0];
    int n_pairs = in_sizes[1];
    int n_mol   = out_size;
    float* out  = (float*)d_out;

    size_t smem = (size_t)n_mol * sizeof(float) + (size_t)n_atoms * sizeof(__half);
    bool fast = (n_atoms <= MAX_ATOMS_COMB) &&
                (n_mol <= (1 << MOL_BITS)) &&
                (smem <= 200 * 1024);

    int prep_n = n_atoms > n_mol ? n_atoms : n_mol;
    prep_kernel<<<(prep_n + 255) / 256, 256>>>(charges, mol_index, n_atoms,
                                               fast ? 1 : 0, out, n_mol);

    if (fast) {
        static int smem_set = -1;
        if ((int)smem > smem_set) {
            cudaFuncSetAttribute(pair_kernel,
                                 cudaFuncAttributeMaxDynamicSharedMemorySize,
                                 (int)smem);
            smem_set = (int)smem;
        }
        pair_kernel<<<148, 1024, smem>>>(pair_dist, pair_first, pair_second,
                                         charges, out, n_pairs, n_mol, n_atoms);
    } else {
        pair_kernel_global<<<296, 1024>>>(pair_dist, pair_first, pair_second,
                                          charges, mol_index, out, n_pairs);
    }
}

// round 6
// speedup vs baseline: 3.2498x; 1.0358x over previous
#include <cuda_runtime.h>
#include <cuda_fp16.h>

#define RADIUS_F 5.0f
#define HALF_ECONV (0.5f * 14.399645f)
#define MAX_ATOMS 262144

// Prep-computed mol decomposition (mol_index is sorted):
//   mol(i) = g_base[i>>4] + g_delta[i]
__device__ unsigned char  g_delta[MAX_ATOMS];
__device__ unsigned short g_base[MAX_ATOMS / 16];

__global__ void prep_kernel(const int* __restrict__ mol_index,
                            int n_atoms, int pack,
                            float* __restrict__ out, int n_mol)
{
    int i = blockIdx.x * blockDim.x + threadIdx.x;
    if (pack && i < n_atoms) {
        int m  = mol_index[i];
        int mb = mol_index[i & ~15];
        g_delta[i] = (unsigned char)(m - mb);
        if ((i & 15) == 0) g_base[i >> 4] = (unsigned short)mb;
    }
    if (i < n_mol) out[i] = 0.0f;
}

__device__ __forceinline__ void accum_pair(
    float r, int fi, int si,
    const __half* __restrict__ qtab,
    const unsigned char* __restrict__ dtab,
    const unsigned short* __restrict__ btab,
    float* __restrict__ bins)
{
    if (r < RADIUS_F) {
        float qi  = __half2float(qtab[fi]);
        float qj  = __half2float(qtab[si]);
        int   mol = (int)btab[fi >> 4] + (int)dtab[fi];
        float scr = 0.5f * (1.0f + cospif(r * (1.0f / RADIUS_F)));
        float e   = qi * qj * __fdividef(scr, r);
        atomicAdd(bins + mol, e);
    }
}

__global__ void __launch_bounds__(1024, 1)
pair_kernel(const float* __restrict__ pair_dist,
            const int*   __restrict__ pair_first,
            const int*   __restrict__ pair_second,
            const float* __restrict__ charges,
            float* __restrict__ out,
            int n_pairs, int n_mol, int n_atoms)
{
    extern __shared__ char smem_raw[];
    __half*         qtab = (__half*)smem_raw;
    unsigned char*  dtab = (unsigned char*)(qtab + n_atoms);
    unsigned short* btab = (unsigned short*)(dtab + n_atoms);
    float*          bins = (float*)(btab + (n_atoms >> 4));

    // --- fill smem tables (all dense, vectorized) ---
    for (int b = threadIdx.x; b < n_mol; b += blockDim.x) bins[b] = 0.0f;
    {
        const float4* c4 = (const float4*)charges;
        __half2* q2 = (__half2*)qtab;
        for (int i = threadIdx.x; i < (n_atoms >> 2); i += blockDim.x) {
            float4 c = c4[i];
            q2[2 * i]     = __floats2half2_rn(c.x, c.y);
            q2[2 * i + 1] = __floats2half2_rn(c.z, c.w);
        }
        const uint4* d16 = (const uint4*)g_delta;
        uint4* sd = (uint4*)dtab;
        for (int i = threadIdx.x; i < (n_atoms >> 4); i += blockDim.x)
            sd[i] = d16[i];
        const unsigned* b2 = (const unsigned*)g_base;
        unsigned* sb = (unsigned*)btab;
        for (int i = threadIdx.x; i < (n_atoms >> 5); i += blockDim.x)
            sb[i] = b2[i];
    }
    __syncthreads();

    const int gtid   = blockIdx.x * blockDim.x + threadIdx.x;
    const int stride = gridDim.x * blockDim.x;
    const int n4     = n_pairs >> 2;

    const float4* __restrict__ pd4 = (const float4*)pair_dist;
    const int4*   __restrict__ pf4 = (const int4*)pair_first;
    const int4*   __restrict__ ps4 = (const int4*)pair_second;

    for (int i = gtid; i < n4; i += stride) {
        float4 d = pd4[i];
        int4   f = pf4[i];
        int4   s = ps4[i];
        accum_pair(d.x, f.x, s.x, qtab, dtab, btab, bins);
        accum_pair(d.y, f.y, s.y, qtab, dtab, btab, bins);
        accum_pair(d.z, f.z, s.z, qtab, dtab, btab, bins);
        accum_pair(d.w, f.w, s.w, qtab, dtab, btab, bins);
    }
    for (int t = (n4 << 2) + gtid; t < n_pairs; t += stride) {
        accum_pair(pair_dist[t], pair_first[t], pair_second[t],
                   qtab, dtab, btab, bins);
    }

    __syncthreads();
    for (int b = threadIdx.x; b < n_mol; b += blockDim.x) {
        float v = bins[b];
        if (v != 0.0f) atomicAdd(out + b, HALF_ECONV * v);
    }
}

// ---- fallback path (shapes outside the fast-path assumptions) ----
__global__ void pair_kernel_global(const float* __restrict__ pair_dist,
                                   const int*   __restrict__ pair_first,
                                   const int*   __restrict__ pair_second,
                                   const float* __restrict__ charges,
                                   const int*   __restrict__ mol_index,
                                   float* __restrict__ out, int n_pairs)
{
    const int gtid   = blockIdx.x * blockDim.x + threadIdx.x;
    const int stride = gridDim.x * blockDim.x;
    for (int i = gtid; i < n_pairs; i += stride) {
        float r = pair_dist[i];
        if (r < RADIUS_F) {
            int   fi  = pair_first[i];
            float qi  = __ldg(charges + fi);
            int   mol = __ldg(mol_index + fi);
            float qj  = __ldg(charges + pair_second[i]);
            float scr = 0.5f * (1.0f + cospif(r * (1.0f / RADIUS_F)));
            float e   = HALF_ECONV * qi * qj * __fdividef(scr, r);
            atomicAdd(out + mol, e);
        }
    }
}

extern "C" void kernel_launch(void* const* d_in, const int* in_sizes, int n_in,
                              void* d_out, int out_size)
{
    const float* charges     = (const float*)d_in[0];
    const float* pair_dist   = (const float*)d_in[1];
    const int*   pair_first  = (const int*)d_in[2];
    const int*   pair_second = (const int*)d_in[3];
    const int*   mol_index   = (const int*)d_in[4];

    int n_atoms = in_sizes[0];
    int n_pairs = in_sizes[1];
    int n_mol   = out_size;
    float* out  = (float*)d_out;

    size_t smem = (size_t)n_atoms * sizeof(__half)          // qtab
                + (size_t)n_atoms                            // dtab
                + (size_t)(n_atoms >> 4) * sizeof(short)     // btab
                + (size_t)n_mol * sizeof(float);             // bins
    bool fast = (n_atoms <= MAX_ATOMS) &&
                ((n_atoms & 31) == 0) &&
                (n_mol <= 65536) &&
                (smem <= 227 * 1024);

    int prep_n = n_atoms > n_mol ? n_atoms : n_mol;
    prep_kernel<<<(prep_n + 255) / 256, 256>>>(mol_index, n_atoms,
                                               fast ? 1 : 0, out, n_mol);

    if (fast) {
        static int smem_set = -1;
        if ((int)smem > smem_set) {
            cudaFuncSetAttribute(pair_kernel,
                                 cudaFuncAttributeMaxDynamicSharedMemorySize,
                                 (int)smem);
            smem_set = (int)smem;
        }
        pair_kernel<<<148, 1024, smem>>>(pair_dist, pair_first, pair_second,
                                         charges, out, n_pairs, n_mol, n_atoms);
    } else {
        pair_kernel_global<<<296, 1024>>>(pair_dist, pair_first, pair_second,
                                          charges, mol_index, out, n_pairs);
    }
}